// round 2
// baseline (speedup 1.0000x reference)
#include <cuda_runtime.h>
#include <cuda_bf16.h>
#include <cstdint>

// Problem constants (fixed by the dataset)
#define NN 50000
#define NE 1600000
#define NB 4
#define NT 50
#define FDT 0.02f

#define CSR_CAP (NE + NN + 2)   // padded: each row rounded up to even #entries

// ---------------- device scratch (static, no allocations) ----------------
__device__ float4 g_csr4[CSR_CAP / 2];   // 2 edges per float4: {w0, src0, w1, src1}
__device__ int    g_row_start[NN + 1];   // padded CSR row offsets (by target), even
__device__ int    g_deg[NN];
__device__ int    g_cursor[NN];
__device__ float  g_v[NN * 4];           // state, [node][batch], updated in place
__device__ float  g_r[2][NN * 4];        // relu(v) rates, ping-pong
__device__ float  g_alpha[NN];           // dt / max(tau, dt)

// ---------------- prep kernels ----------------
__global__ void init_kernel(const float* __restrict__ bias,
                            const float* __restrict__ tc) {
    int i = blockIdx.x * blockDim.x + threadIdx.x;
    if (i < NN) {
        g_deg[i] = 0;
        g_cursor[i] = 0;
        g_alpha[i] = FDT / fmaxf(tc[i], FDT);
        float b = bias[i];
        float rb = fmaxf(b, 0.0f);
        *reinterpret_cast<float4*>(&g_v[4 * i])    = make_float4(b, b, b, b);
        *reinterpret_cast<float4*>(&g_r[0][4 * i]) = make_float4(rb, rb, rb, rb);
    }
}

__global__ void hist_kernel(const int* __restrict__ tgt) {
    int i = blockIdx.x * blockDim.x + threadIdx.x;
    if (i < NE) atomicAdd(&g_deg[tgt[i]], 1);
}

// Single-block exclusive scan over padded degrees -> g_row_start
__global__ void scan_kernel() {
    __shared__ int warp_sums[32];
    __shared__ int s_carry;
    const int tid = threadIdx.x;
    const int lane = tid & 31, wid = tid >> 5;
    if (tid == 0) s_carry = 0;
    __syncthreads();
    for (int base = 0; base < NN; base += 1024) {
        int i = base + tid;
        int v = (i < NN) ? ((g_deg[i] + 1) & ~1) : 0;   // pad to even
        int x = v;
        #pragma unroll
        for (int o = 1; o < 32; o <<= 1) {
            int y = __shfl_up_sync(0xffffffffu, x, o);
            if (lane >= o) x += y;
        }
        if (lane == 31) warp_sums[wid] = x;
        __syncthreads();
        if (wid == 0) {
            int w = warp_sums[lane];
            #pragma unroll
            for (int o = 1; o < 32; o <<= 1) {
                int y = __shfl_up_sync(0xffffffffu, w, o);
                if (lane >= o) w += y;
            }
            warp_sums[lane] = w;
        }
        __syncthreads();
        int warp_off = (wid == 0) ? 0 : warp_sums[wid - 1];
        int incl = x + warp_off;
        int carry = s_carry;
        if (i < NN) g_row_start[i] = carry + incl - v;
        __syncthreads();
        if (tid == 1023) s_carry = carry + incl;
        __syncthreads();
    }
    if (tid == 0) g_row_start[NN] = s_carry;
}

// Write the single zero-weight pad entry for odd-degree rows
__global__ void fill_pad_kernel() {
    int i = blockIdx.x * blockDim.x + threadIdx.x;
    if (i >= NN) return;
    int d = g_deg[i];
    if (d & 1) {
        float2* csr2 = reinterpret_cast<float2*>(g_csr4);
        csr2[g_row_start[i] + d] = make_float2(0.0f, __int_as_float(0));
    }
}

__global__ void scatter_kernel(const int* __restrict__ src, const int* __restrict__ tgt,
                               const float* __restrict__ sign, const float* __restrict__ cnt,
                               const float* __restrict__ strg) {
    int i = blockIdx.x * blockDim.x + threadIdx.x;
    if (i >= NE) return;
    float w = sign[i] * fmaxf(cnt[i], 0.0f) * fmaxf(strg[i], 0.0f);
    int t = tgt[i];
    int pos = atomicAdd(&g_cursor[t], 1);
    float2* csr2 = reinterpret_cast<float2*>(g_csr4);
    csr2[g_row_start[t] + pos] = make_float2(w, __int_as_float(src[i]));
}

// ---------------- main step: warp-per-row CSR SpMM + Euler update ----------------
__global__ void __launch_bounds__(128, 8) step_kernel(const float* __restrict__ bias,
                                                      const float* __restrict__ x,
                                                      float* __restrict__ out,
                                                      int t, int parity) {
    const float* __restrict__ rates     = g_r[parity];
    float* __restrict__       rates_new = g_r[parity ^ 1];

    const int warp = blockIdx.x * (blockDim.x >> 5) + (threadIdx.x >> 5);
    const int lane = threadIdx.x & 31;
    if (warp >= NN) return;
    const int row = warp;
    const int s = __ldg(&g_row_start[row]);
    const int e = __ldg(&g_row_start[row + 1]);

    float ax = 0.f, ay = 0.f, az = 0.f, aw = 0.f;
    // 2 edges per lane per iteration; s,e are even, entries 16B aligned
    for (int i = (s >> 1) + lane; i < (e >> 1); i += 32) {
        float4 p = __ldcs(&g_csr4[i]);               // stream: keep L1 for rates
        int s0 = __float_as_int(p.y);
        int s1 = __float_as_int(p.w);
        float4 r0 = *reinterpret_cast<const float4*>(rates + 4 * s0);
        float4 r1 = *reinterpret_cast<const float4*>(rates + 4 * s1);
        ax = fmaf(r0.x, p.x, ax);
        ay = fmaf(r0.y, p.x, ay);
        az = fmaf(r0.z, p.x, az);
        aw = fmaf(r0.w, p.x, aw);
        ax = fmaf(r1.x, p.z, ax);
        ay = fmaf(r1.y, p.z, ay);
        az = fmaf(r1.z, p.z, az);
        aw = fmaf(r1.w, p.z, aw);
    }
    // butterfly: all lanes end with full sums
    #pragma unroll
    for (int o = 16; o; o >>= 1) {
        ax += __shfl_xor_sync(0xffffffffu, ax, o);
        ay += __shfl_xor_sync(0xffffffffu, ay, o);
        az += __shfl_xor_sync(0xffffffffu, az, o);
        aw += __shfl_xor_sync(0xffffffffu, aw, o);
    }
    if (lane < 4) {
        const int b = lane;
        float sum = (b == 0) ? ax : (b == 1) ? ay : (b == 2) ? az : aw;
        float alpha = __ldg(&g_alpha[row]);
        float bi    = __ldg(&bias[row]);
        float vo    = g_v[4 * row + b];
        float xv    = __ldcs(&x[(b * NT + t) * NN + row]);
        float vn = fmaf(alpha, bi - vo + sum + xv, vo);
        float rn = fmaxf(vn, 0.f);
        g_v[4 * row + b]       = vn;
        rates_new[4 * row + b] = rn;
        out[(b * NT + t) * NN + row] = rn;
    }
}

// ---------------- launch ----------------
extern "C" void kernel_launch(void* const* d_in, const int* in_sizes, int n_in,
                              void* d_out, int out_size) {
    const float* x      = (const float*)d_in[0];  // [B,T,N]
    const float* bias   = (const float*)d_in[1];  // [N]
    const float* tcst   = (const float*)d_in[2];  // [N]
    const float* sign   = (const float*)d_in[3];  // [E]
    const float* cnt    = (const float*)d_in[4];  // [E]
    const float* strg   = (const float*)d_in[5];  // [E]
    const int*   srcidx = (const int*)d_in[6];    // [E]
    const int*   tgtidx = (const int*)d_in[7];    // [E]
    float* out = (float*)d_out;                   // [B,T,N]

    const int nblk = (NN + 255) / 256;
    const int eblk = (NE + 255) / 256;

    init_kernel<<<nblk, 256>>>(bias, tcst);
    hist_kernel<<<eblk, 256>>>(tgtidx);
    scan_kernel<<<1, 1024>>>();
    fill_pad_kernel<<<nblk, 256>>>();
    scatter_kernel<<<eblk, 256>>>(srcidx, tgtidx, sign, cnt, strg);

    // warp per row: 4 rows per 128-thread block
    const int sblk = (NN + 3) / 4;
    for (int t = 0; t < NT; t++) {
        step_kernel<<<sblk, 128>>>(bias, x, out, t, t & 1);
    }
    (void)in_sizes; (void)n_in; (void)out_size;
}

// round 3
// speedup vs baseline: 2.4155x; 2.4155x over previous
#include <cuda_runtime.h>
#include <cuda_bf16.h>
#include <cstdint>

// Problem constants (fixed by the dataset)
#define NN 50000
#define NE 1600000
#define NT 50
#define FDT 0.02f

// Persistent-kernel geometry: 296 = 148 SMs * 2 blocks, guaranteed co-resident
#define PBLK 296
#define THREADS 512
#define GPB (THREADS / 8)           // 64 groups of 8 lanes per block
#define NGROUPS (PBLK * GPB)        // 18944
#define MAXK 3                      // ceil(NN / NGROUPS)

// ---------------- device scratch (static, no allocations) ----------------
__device__ float2 g_csr[NE];            // per edge: {weight, bitcast(src)} sorted by target
__device__ int    g_row_start[NN + 1];
__device__ int    g_deg[NN];
__device__ int    g_cursor[NN];
__device__ float  g_r[2][NN * 4];       // relu(v) rates, ping-pong, layout [node][batch]
__device__ float  g_alpha[NN];          // dt / max(tau, dt)
__device__ int    g_bar;                // global barrier arrival counter

// ---------------- prep kernels ----------------
__global__ void init_kernel(const float* __restrict__ bias,
                            const float* __restrict__ tc) {
    int i = blockIdx.x * blockDim.x + threadIdx.x;
    if (i == 0) g_bar = 0;
    if (i < NN) {
        g_deg[i] = 0;
        g_cursor[i] = 0;
        g_alpha[i] = FDT / fmaxf(tc[i], FDT);
        float rb = fmaxf(bias[i], 0.0f);
        *reinterpret_cast<float4*>(&g_r[0][4 * i]) = make_float4(rb, rb, rb, rb);
    }
}

__global__ void hist_kernel(const int* __restrict__ tgt) {
    int i = blockIdx.x * blockDim.x + threadIdx.x;
    if (i < NE) atomicAdd(&g_deg[tgt[i]], 1);
}

// Single-block exclusive scan over g_deg -> g_row_start
__global__ void scan_kernel() {
    __shared__ int warp_sums[32];
    __shared__ int s_carry;
    const int tid = threadIdx.x;
    const int lane = tid & 31, wid = tid >> 5;
    if (tid == 0) s_carry = 0;
    __syncthreads();
    for (int base = 0; base < NN; base += 1024) {
        int i = base + tid;
        int v = (i < NN) ? g_deg[i] : 0;
        int x = v;
        #pragma unroll
        for (int o = 1; o < 32; o <<= 1) {
            int y = __shfl_up_sync(0xffffffffu, x, o);
            if (lane >= o) x += y;
        }
        if (lane == 31) warp_sums[wid] = x;
        __syncthreads();
        if (wid == 0) {
            int w = warp_sums[lane];
            #pragma unroll
            for (int o = 1; o < 32; o <<= 1) {
                int y = __shfl_up_sync(0xffffffffu, w, o);
                if (lane >= o) w += y;
            }
            warp_sums[lane] = w;
        }
        __syncthreads();
        int warp_off = (wid == 0) ? 0 : warp_sums[wid - 1];
        int incl = x + warp_off;
        int carry = s_carry;
        if (i < NN) g_row_start[i] = carry + incl - v;
        __syncthreads();
        if (tid == 1023) s_carry = carry + incl;
        __syncthreads();
    }
    if (tid == 0) g_row_start[NN] = s_carry;
}

__global__ void scatter_kernel(const int* __restrict__ src, const int* __restrict__ tgt,
                               const float* __restrict__ sign, const float* __restrict__ cnt,
                               const float* __restrict__ strg) {
    int i = blockIdx.x * blockDim.x + threadIdx.x;
    if (i >= NE) return;
    float w = sign[i] * fmaxf(cnt[i], 0.0f) * fmaxf(strg[i], 0.0f);
    int t = tgt[i];
    int pos = atomicAdd(&g_cursor[t], 1);
    g_csr[g_row_start[t] + pos] = make_float2(w, __int_as_float(src[i]));
}

// ---------------- persistent kernel: all 50 steps, software global barrier ----------------
__global__ void __launch_bounds__(THREADS, 2) net_kernel(const float* __restrict__ bias,
                                                         const float* __restrict__ x,
                                                         float* __restrict__ out) {
    const int tid = threadIdx.x;
    const int gid = blockIdx.x * GPB + (tid >> 3);   // global 8-lane group id
    const int lig = tid & 7;                         // lane in group (batch id if < 4)
    const unsigned gmask = 0xFFu << (((tid & 31) >> 3) * 8);

    // hoisted per-row invariants (live in registers for all 50 steps)
    int   rows[MAXK], rs[MAXK], re[MAXK];
    bool  val[MAXK];
    float vb[MAXK], bi[MAXK], al[MAXK];
    #pragma unroll
    for (int k = 0; k < MAXK; k++) {
        int r = gid + k * NGROUPS;
        bool ok = r < NN;
        val[k] = ok;
        rows[k] = ok ? r : 0;
        rs[k] = ok ? __ldg(&g_row_start[r]) : 0;
        re[k] = ok ? __ldg(&g_row_start[r + 1]) : 0;
        float b = ok ? __ldg(&bias[r]) : 0.0f;
        bi[k] = b;
        vb[k] = b;                                   // v starts at bias
        al[k] = ok ? __ldg(&g_alpha[r]) : 0.0f;
    }

    for (int t = 0; t < NT; t++) {
        const float* __restrict__ rates = g_r[t & 1];
        float* __restrict__       rnew  = g_r[(t & 1) ^ 1];

        // prefetch stimulus for this step (batch = lig for lanes 0..3)
        float xs[MAXK];
        #pragma unroll
        for (int k = 0; k < MAXK; k++)
            xs[k] = (val[k] && lig < 4) ? __ldcs(&x[(lig * NT + t) * NN + rows[k]]) : 0.0f;

        #pragma unroll
        for (int k = 0; k < MAXK; k++) {
            float ax = 0.f, ay = 0.f, az = 0.f, aw = 0.f;
            for (int i = rs[k] + lig; i < re[k]; i += 8) {
                float2 p = __ldcs(&g_csr[i]);
                const float4 r4 =
                    *reinterpret_cast<const float4*>(rates + 4 * __float_as_int(p.y));
                ax = fmaf(r4.x, p.x, ax);
                ay = fmaf(r4.y, p.x, ay);
                az = fmaf(r4.z, p.x, az);
                aw = fmaf(r4.w, p.x, aw);
            }
            // reduce within the 8-lane group (all lanes of group converge here)
            #pragma unroll
            for (int o = 4; o; o >>= 1) {
                ax += __shfl_xor_sync(gmask, ax, o, 8);
                ay += __shfl_xor_sync(gmask, ay, o, 8);
                az += __shfl_xor_sync(gmask, az, o, 8);
                aw += __shfl_xor_sync(gmask, aw, o, 8);
            }
            if (val[k] && lig < 4) {
                float sum = (lig == 0) ? ax : (lig == 1) ? ay : (lig == 2) ? az : aw;
                float vo = vb[k];
                float vn = fmaf(al[k], bi[k] - vo + sum + xs[k], vo);
                vb[k] = vn;
                float rn = fmaxf(vn, 0.f);
                rnew[4 * rows[k] + lig] = rn;
                __stcs(&out[(lig * NT + t) * NN + rows[k]], rn);
            }
        }

        // global barrier between steps (not after the last)
        if (t != NT - 1) {
            __threadfence();          // publish rate stores to L2 (also flushes L1)
            __syncthreads();
            if (tid == 0) {
                atomicAdd(&g_bar, 1);
                const int target = (t + 1) * PBLK;
                volatile int* pb = &g_bar;
                while (*pb < target) { }
            }
            __syncthreads();
        }
    }
}

// ---------------- launch ----------------
extern "C" void kernel_launch(void* const* d_in, const int* in_sizes, int n_in,
                              void* d_out, int out_size) {
    const float* x      = (const float*)d_in[0];  // [B,T,N]
    const float* bias   = (const float*)d_in[1];  // [N]
    const float* tcst   = (const float*)d_in[2];  // [N]
    const float* sign   = (const float*)d_in[3];  // [E]
    const float* cnt    = (const float*)d_in[4];  // [E]
    const float* strg   = (const float*)d_in[5];  // [E]
    const int*   srcidx = (const int*)d_in[6];    // [E]
    const int*   tgtidx = (const int*)d_in[7];    // [E]
    float* out = (float*)d_out;                   // [B,T,N]

    const int nblk = (NN + 255) / 256;
    const int eblk = (NE + 255) / 256;

    init_kernel<<<nblk, 256>>>(bias, tcst);
    hist_kernel<<<eblk, 256>>>(tgtidx);
    scan_kernel<<<1, 1024>>>();
    scatter_kernel<<<eblk, 256>>>(srcidx, tgtidx, sign, cnt, strg);

    net_kernel<<<PBLK, THREADS>>>(bias, x, out);

    (void)in_sizes; (void)n_in; (void)out_size;
}